// round 11
// baseline (speedup 1.0000x reference)
#include <cuda_runtime.h>

#define DF __device__ __forceinline__
typedef unsigned long long ull;

static constexpr int BATCH  = 8;
static constexpr int N0     = 4096;
static constexpr int IN_DIM = 1024;
static constexpr int EMB    = 512;
static constexpr int HEADS  = 4;
static constexpr int DH     = 128;
static constexpr int LM     = 256;    // landmarks
static constexpr int NP     = 4352;   // padded seq
static constexpr int NT     = 4097;   // cls + tokens
static constexpr int PADR   = 255;    // left zero pad
static constexpr int LSEG   = 17;     // NP / LM
static constexpr int NITER  = 6;
static constexpr int RESK   = 33;
static constexpr float QSCALE = 0.08838834764831845f; // 128^-0.5

// ------------------------- scratch (device globals; no allocs) ---------------
__device__ float g_H  [BATCH*NT*EMB];
__device__ float g_LN [BATCH*NP*EMB];
__device__ float g_Q  [BATCH*HEADS*NP*DH];
__device__ float g_K  [BATCH*HEADS*NP*DH];
__device__ float g_V  [BATCH*HEADS*NP*DH];
__device__ float g_QL [BATCH*HEADS*LM*DH];
__device__ float g_KL [BATCH*HEADS*LM*DH];
__device__ float g_A1 [BATCH*HEADS*NP*LM];
__device__ float g_A3 [BATCH*HEADS*LM*NP];
__device__ float g_A2 [BATCH*HEADS*LM*LM];
__device__ float g_Za [BATCH*HEADS*LM*LM];
__device__ float g_Zb [BATCH*HEADS*LM*LM];
__device__ float g_T1 [BATCH*HEADS*LM*LM];
__device__ float g_T2 [BATCH*HEADS*LM*LM];
__device__ float g_T3 [BATCH*HEADS*LM*LM];
__device__ float g_AV [BATCH*HEADS*LM*DH];
__device__ float g_AVp[4*BATCH*HEADS*LM*DH];
__device__ float g_ZAV[BATCH*HEADS*LM*DH];
__device__ float g_O  [BATCH*NP*EMB];
__device__ float g_mr [BATCH*HEADS];
__device__ float g_mc [BATCH*HEADS];
__device__ float g_den[1];

// ------------------------- f32x2 helpers -------------------------------------
DF ull dup2(float x) { ull r; asm("mov.b64 %0, {%1, %1};" : "=l"(r) : "f"(x)); return r; }
DF void ffma2(ull& d, ull a, ull b) {
    asm("fma.rn.f32x2 %0, %1, %2, %0;" : "+l"(d) : "l"(a), "l"(b));
}
DF void unpk(ull v, float& a, float& b) {
    asm("mov.b64 {%0, %1}, %2;" : "=f"(a), "=f"(b) : "l"(v));
}

// ------------------------- block reductions (256 threads) --------------------
DF float blockReduceSum256(float v) {
    __shared__ float sh[256];
    int t = threadIdx.x;
    sh[t] = v; __syncthreads();
#pragma unroll
    for (int s = 128; s > 0; s >>= 1) { if (t < s) sh[t] += sh[t + s]; __syncthreads(); }
    float r = sh[0]; __syncthreads(); return r;
}
DF float blockReduceMax256(float v) {
    __shared__ float sh[256];
    int t = threadIdx.x;
    sh[t] = v; __syncthreads();
#pragma unroll
    for (int s = 128; s > 0; s >>= 1) { if (t < s) sh[t] = fmaxf(sh[t], sh[t + s]); __syncthreads(); }
    float r = sh[0]; __syncthreads(); return r;
}

// ------------------------- misc small kernels --------------------------------
__global__ void set_cls_kernel(const float* __restrict__ cls) {
    g_H[(long)blockIdx.x * NT * EMB + threadIdx.x] = cls[threadIdx.x];
}

__global__ void ln_pad_kernel(const float* __restrict__ g, const float* __restrict__ bt) {
    long row = blockIdx.x;                 // 0 .. BATCH*NP-1
    int b = (int)(row / NP), i = (int)(row % NP);
    float* dst = g_LN + row * EMB;
    int t = threadIdx.x;                   // 256 threads
    if (i < PADR) { dst[t] = 0.f; dst[t + 256] = 0.f; return; }
    const float* src = g_H + ((long)b * NT + (i - PADR)) * EMB;
    float x0 = src[t], x1 = src[t + 256];
    float mu  = blockReduceSum256(x0 + x1) * (1.f / EMB);
    float var = blockReduceSum256(x0 * x0 + x1 * x1) * (1.f / EMB) - mu * mu;
    float rstd = rsqrtf(var + 1e-5f);
    dst[t]       = (x0 - mu) * rstd * g[t]       + bt[t];
    dst[t + 256] = (x1 - mu) * rstd * g[t + 256] + bt[t + 256];
}

__global__ void landmarks_kernel() {
    int z = blockIdx.y, m = blockIdx.x, d = threadIdx.x; // 128 threads
    const float* q = g_Q + ((long)z * NP + m * LSEG) * DH + d;
    const float* k = g_K + ((long)z * NP + m * LSEG) * DH + d;
    float sq = 0.f, sk = 0.f;
#pragma unroll
    for (int j = 0; j < LSEG; j++) { sq += q[(long)j * DH]; sk += k[(long)j * DH]; }
    g_QL[((long)z * LM + m) * DH + d] = sq * (1.f / LSEG);
    g_KL[((long)z * LM + m) * DH + d] = sk * (1.f / LSEG);
}

template <int NIT>
__global__ void softmax_rows(float* __restrict__ base, int cols, int ld) {
    float* p = base + (long)blockIdx.x * ld;
    int t = threadIdx.x;                   // 256 threads
    float v[NIT];
    float mx = -1e30f;
#pragma unroll
    for (int i = 0; i < NIT; i++) {
        int j = i * 256 + t;
        v[i] = (j < cols) ? p[j] : -1e30f;
        mx = fmaxf(mx, v[i]);
    }
    mx = blockReduceMax256(mx);
    float sum = 0.f;
#pragma unroll
    for (int i = 0; i < NIT; i++) {
        int j = i * 256 + t;
        v[i] = (j < cols) ? __expf(v[i] - mx) : 0.f;
        sum += v[i];
    }
    sum = blockReduceSum256(sum);
    float inv = 1.f / sum;
#pragma unroll
    for (int i = 0; i < NIT; i++) {
        int j = i * 256 + t;
        if (j < cols) p[j] = v[i] * inv;
    }
}

__global__ void denom1_kernel() {
    int z = blockIdx.x, t = threadIdx.x;   // 256 threads
    const float* a = g_A2 + (long)z * LM * LM;
    float cs = 0.f, rs = 0.f;
    for (int i = 0; i < LM; i++) cs += fabsf(a[(long)i * LM + t]);
    for (int j = 0; j < LM; j++) rs += fabsf(a[(long)t * LM + j]);
    float mc = blockReduceMax256(cs);
    float mr = blockReduceMax256(rs);
    if (t == 0) { g_mc[z] = mc; g_mr[z] = mr; }
}
__global__ void denom2_kernel() {
    int t = threadIdx.x;                   // 32 threads
    float mc = g_mc[t], mr = g_mr[t];
#pragma unroll
    for (int o = 16; o > 0; o >>= 1) {
        mc = fmaxf(mc, __shfl_down_sync(0xffffffffu, mc, o));
        mr = fmaxf(mr, __shfl_down_sync(0xffffffffu, mr, o));
    }
    if (t == 0) g_den[0] = mc * mr;
}
__global__ void z0_kernel(float* __restrict__ z0) {
    int z = blockIdx.y, m = blockIdx.x, j = threadIdx.x;  // 256 threads
    float inv = 1.f / g_den[0];
    z0[((long)z * LM + m) * LM + j] = g_A2[((long)z * LM + j) * LM + m] * inv;
}

__global__ void resconv_kernel(const float* __restrict__ res_k) {
    int i = blockIdx.x, z = blockIdx.y, d = threadIdx.x;  // 128 threads
    int b = z / HEADS, h = z % HEADS;
    const float* kk = res_k + h * RESK;
    float acc = 0.f;
#pragma unroll
    for (int t = 0; t < RESK; t++) {
        int it = i + t - (RESK / 2);
        if (it >= 0 && it < NP) acc += kk[t] * g_V[((long)z * NP + it) * DH + d];
    }
    g_O[((long)b * NP + i) * EMB + h * DH + d] += acc;
}

__global__ void ppeg_kernel(const float* __restrict__ k7, const float* __restrict__ b7,
                            const float* __restrict__ k5, const float* __restrict__ b5,
                            const float* __restrict__ k3, const float* __restrict__ b3) {
    int pos = blockIdx.x, b = blockIdx.y, c = threadIdx.x; // 512 threads
    int y = pos >> 6, x = pos & 63;
    const float* fb = g_H + ((long)b * NT + 1) * EMB + c;
    float acc = fb[(long)pos * EMB] + b7[c] + b5[c] + b3[c];
    const float* w7 = k7 + c * 49;
#pragma unroll
    for (int ky = 0; ky < 7; ky++) {
        int py = y + ky - 3;
        if ((unsigned)py >= 64u) continue;
#pragma unroll
        for (int kx = 0; kx < 7; kx++) {
            int px = x + kx - 3;
            if ((unsigned)px >= 64u) continue;
            acc += w7[ky * 7 + kx] * fb[(long)(py * 64 + px) * EMB];
        }
    }
    const float* w5 = k5 + c * 25;
#pragma unroll
    for (int ky = 0; ky < 5; ky++) {
        int py = y + ky - 2;
        if ((unsigned)py >= 64u) continue;
#pragma unroll
        for (int kx = 0; kx < 5; kx++) {
            int px = x + kx - 2;
            if ((unsigned)px >= 64u) continue;
            acc += w5[ky * 5 + kx] * fb[(long)(py * 64 + px) * EMB];
        }
    }
    const float* w3 = k3 + c * 9;
#pragma unroll
    for (int ky = 0; ky < 3; ky++) {
        int py = y + ky - 1;
        if ((unsigned)py >= 64u) continue;
#pragma unroll
        for (int kx = 0; kx < 3; kx++) {
            int px = x + kx - 1;
            if ((unsigned)px >= 64u) continue;
            acc += w3[ky * 3 + kx] * fb[(long)(py * 64 + px) * EMB];
        }
    }
    g_LN[((long)b * N0 + pos) * EMB + c] = acc;
}
__global__ void ppeg_copy_kernel() {
    long idx = (long)blockIdx.x * blockDim.x + threadIdx.x;
    long per = (long)N0 * EMB;
    int b = (int)(idx / per); long rem = idx % per;
    g_H[((long)b * NT + 1) * EMB + rem] = g_LN[idx];
}

__global__ void final_kernel(const float* __restrict__ ng, const float* __restrict__ nb,
                             const float* __restrict__ cw, const float* __restrict__ cb,
                             float* __restrict__ out) {
    int b = blockIdx.x, t = threadIdx.x;   // 256 threads
    const float* src = g_H + (long)b * NT * EMB;
    float x0 = src[t], x1 = src[t + 256];
    float mu  = blockReduceSum256(x0 + x1) * (1.f / EMB);
    float var = blockReduceSum256(x0 * x0 + x1 * x1) * (1.f / EMB) - mu * mu;
    float rstd = rsqrtf(var + 1e-5f);
    float v0 = (x0 - mu) * rstd * ng[t]       + nb[t];
    float v1 = (x1 - mu) * rstd * ng[t + 256] + nb[t + 256];
    float dot = blockReduceSum256(v0 * cw[t] + v1 * cw[t + 256]);
    if (t == 0) out[b] = dot + cb[0];
}

__global__ void av_reduce_kernel() {
    long i = (long)blockIdx.x * 256 + threadIdx.x;
    const long T = (long)BATCH * HEADS * LM * DH;
    g_AV[i] = g_AVp[i] + g_AVp[i + T] + g_AVp[i + 2 * T] + g_AVp[i + 3 * T];
}

// ------------------------- 128x128x16 f32x2 inner step -----------------------
DF void mm16(const float (&As)[16][128], const float (&Bs)[16][128],
             int ty8, int tx8, ull (&acc)[8][4]) {
#pragma unroll
    for (int k = 0; k < 16; k++) {
        float4 a0 = *(const float4*)(&As[k][ty8]);
        float4 a1 = *(const float4*)(&As[k][ty8 + 4]);
        ulonglong2 b0 = *(const ulonglong2*)(&Bs[k][tx8]);
        ulonglong2 b1 = *(const ulonglong2*)(&Bs[k][tx8 + 4]);
        ull aD[8];
        aD[0] = dup2(a0.x); aD[1] = dup2(a0.y); aD[2] = dup2(a0.z); aD[3] = dup2(a0.w);
        aD[4] = dup2(a1.x); aD[5] = dup2(a1.y); aD[6] = dup2(a1.z); aD[7] = dup2(a1.w);
        ull bP[4] = {b0.x, b0.y, b1.x, b1.y};
#pragma unroll
        for (int i = 0; i < 8; i++)
#pragma unroll
            for (int j = 0; j < 4; j++) ffma2(acc[i][j], aD[i], bP[j]);
    }
}

// ------------------------- batched GEMM 128x128 ------------------------------
// C = s*(A@B[^T]) + t*A  (batched over z; optional split-K into partial bufs)
struct BG2 {
    const float* A; const float* B; float* C;
    int K, lda, ldb, ldc;
    long sA, sB, sCb, sCh;     // C base = (z/HEADS)*sCb + (z%HEADS)*sCh
    float s, t;
    int split; long sSplit;    // split-K partials
};

template <bool TRANSB, bool ADDT>
__global__ __launch_bounds__(256, 2) void g128_bat(BG2 p) {
    __shared__ float As[2][16][128];
    __shared__ float Bs[2][16][128];

    int zz = blockIdx.z;
    int sp = zz % p.split;
    int z  = zz / p.split;
    const float* Ab = p.A + (long)z * p.sA;
    const float* Bb = p.B + (long)z * p.sB;
    float* Cb = p.C + (long)(z / HEADS) * p.sCb + (long)(z % HEADS) * p.sCh
                    + (long)sp * p.sSplit;
    int kchunk = p.K / p.split;
    int kb = sp * kchunk, ke = kb + kchunk;

    int bm = blockIdx.y * 128, bn = blockIdx.x * 128;
    int tid = threadIdx.x;
    int tx8 = (tid & 15) * 8, ty8 = (tid >> 4) * 8;

    // A loader: m fixed per thread, two k-quads
    int am  = tid & 127;
    int aq0 = (tid >> 7) * 4;             // {0,4}; second load at +8
    const float* Arow = Ab + (long)(bm + am) * p.lda;

    // B loader
    int bkr = 0, bnc = 0, bnr = 0, bq0 = 0;
    const float* Brow = nullptr;
    if (!TRANSB) {
        bkr = tid >> 5;                    // 0..7 (second at +8)
        bnc = (tid & 31) * 4;
    } else {
        bnr = tid & 127;
        bq0 = (tid >> 7) * 4;
        Brow = Bb + (long)(bn + bnr) * p.ldb;
    }

    ull acc[8][4] = {};
    float4 ra0, ra1, rb0, rb1;

    auto ldAB = [&](int k0) {
        ra0 = *(const float4*)(Arow + k0 + aq0);
        ra1 = *(const float4*)(Arow + k0 + aq0 + 8);
        if (!TRANSB) {
            rb0 = *(const float4*)(Bb + (long)(k0 + bkr) * p.ldb + bn + bnc);
            rb1 = *(const float4*)(Bb + (long)(k0 + bkr + 8) * p.ldb + bn + bnc);
        } else {
            rb0 = *(const float4*)(Brow + k0 + bq0);
            rb1 = *(const float4*)(Brow + k0 + bq0 + 8);
        }
    };
    auto stAB = [&](int buf) {
        As[buf][aq0 + 0][am] = ra0.x; As[buf][aq0 + 1][am] = ra0.y;
        As[buf][aq0 + 2][am] = ra0.z; As[buf][aq0 + 3][am] = ra0.w;
        As[buf][aq0 + 8][am] = ra1.x; As[buf][aq0 + 9][am] = ra1.y;
        As[buf][aq0 +10][am] = ra1.z; As[buf][aq0 +11][am] = ra1.w;
        if (!TRANSB) {
            *(float4*)(&Bs[buf][bkr][bnc])     = rb0;
            *(float4*)(&Bs[buf][bkr + 8][bnc]) = rb1;
        } else {
            Bs[buf][bq0 + 0][bnr] = rb0.x; Bs[buf][bq0 + 1][bnr] = rb0.y;
            Bs[buf][bq0 + 2][bnr] = rb0.z; Bs[buf][bq0 + 3][bnr] = rb0.w;
            Bs[buf][bq0 + 8][bnr] = rb1.x; Bs[buf][bq0 + 9][bnr] = rb1.y;
            Bs[buf][bq0 +10][bnr] = rb1.z; Bs[buf][bq0 +11][bnr] = rb1.w;
        }
    };

    ldAB(kb); stAB(0);
    __syncthreads();
    int buf = 0;
    for (int k0 = kb; k0 < ke; k0 += 16) {
        bool more = (k0 + 16) < ke;
        if (more) ldAB(k0 + 16);
        mm16(As[buf], Bs[buf], ty8, tx8, acc);
        if (more) { stAB(buf ^ 1); __syncthreads(); buf ^= 1; }
    }

#pragma unroll
    for (int i = 0; i < 8; i++) {
        long r = bm + ty8 + i;
        float v[8];
#pragma unroll
        for (int j2 = 0; j2 < 4; j2++) unpk(acc[i][j2], v[2 * j2], v[2 * j2 + 1]);
#pragma unroll
        for (int j = 0; j < 8; j++) v[j] *= p.s;
        if (ADDT) {
            float4 t0 = *(const float4*)(Ab + r * p.lda + bn + tx8);
            float4 t1 = *(const float4*)(Ab + r * p.lda + bn + tx8 + 4);
            v[0] += p.t * t0.x; v[1] += p.t * t0.y; v[2] += p.t * t0.z; v[3] += p.t * t0.w;
            v[4] += p.t * t1.x; v[5] += p.t * t1.y; v[6] += p.t * t1.z; v[7] += p.t * t1.w;
        }
        *(float4*)(Cb + r * p.ldc + bn + tx8)     = make_float4(v[0], v[1], v[2], v[3]);
        *(float4*)(Cb + r * p.ldc + bn + tx8 + 4) = make_float4(v[4], v[5], v[6], v[7]);
    }
}

// ------------------------- big weight GEMMs 128x128 --------------------------
// MODE 0: FEW  (X @ few_w + bias) -> g_H rows 1..4096 per batch
// MODE 1: QKV  (g_LN @ qkv_w)     -> scattered to g_Q(*scale)/g_K/g_V
// MODE 2: PROJ (g_O[pad rows] @ out_w + bias) accumulated into g_H
template <int MODE>
__global__ __launch_bounds__(256, 2) void g128_big(const float* __restrict__ Ax,
                                                   const float* __restrict__ W,
                                                   const float* __restrict__ bias) {
    constexpr int Kd = (MODE == 0) ? IN_DIM : EMB;
    constexpr int Nd = (MODE == 1) ? 3 * EMB : EMB;
    constexpr int Md = (MODE == 0) ? BATCH * N0 : (MODE == 1 ? BATCH * NP : BATCH * NT);

    __shared__ float As[2][16][128];
    __shared__ float Bs[2][16][128];

    int bm = blockIdx.y * 128, bn = blockIdx.x * 128;
    int tid = threadIdx.x;
    int tx8 = (tid & 15) * 8, ty8 = (tid >> 4) * 8;

    int am  = tid & 127;
    int aq0 = (tid >> 7) * 4;
    bool avalid = (bm + am) < Md;
    const float* Arow;
    {
        int r = bm + am; if (r >= Md) r = Md - 1;
        if (MODE == 2) {
            int b = r / NT, i = r % NT;
            Arow = g_O + ((long)(b * NP + PADR + i)) * EMB;
        } else if (MODE == 1) {
            Arow = g_LN + (long)r * Kd;
        } else {
            Arow = Ax + (long)r * Kd;
        }
    }
    int bkr = tid >> 5;
    int bnc = (tid & 31) * 4;

    ull acc[8][4] = {};
    float4 ra0, ra1, rb0, rb1;

    auto ldAB = [&](int k0) {
        ra0 = *(const float4*)(Arow + k0 + aq0);
        ra1 = *(const float4*)(Arow + k0 + aq0 + 8);
        if (!avalid) { ra0 = make_float4(0, 0, 0, 0); ra1 = make_float4(0, 0, 0, 0); }
        rb0 = *(const float4*)(W + (long)(k0 + bkr) * Nd + bn + bnc);
        rb1 = *(const float4*)(W + (long)(k0 + bkr + 8) * Nd + bn + bnc);
    };
    auto stAB = [&](int buf) {
        As[buf][aq0 + 0][am] = ra0.x; As[buf][aq0 + 1][am] = ra0.y;
        As[buf][aq0 + 2][am] = ra0.z; As[buf][aq0 + 3][am] = ra0.w;
        As[buf][aq0 + 8][am] = ra1.x; As[buf][aq0 + 9][am] = ra1.y;
        As[buf][aq0 +10][am] = ra1.z; As[buf][aq0 +11][am] = ra1.w;
        *(float4*)(&Bs[buf][bkr][bnc])     = rb0;
        *(float4*)(&Bs[buf][bkr + 8][bnc]) = rb1;
    };

    ldAB(0); stAB(0);
    __syncthreads();
    int buf = 0;
    for (int k0 = 0; k0 < Kd; k0 += 16) {
        bool more = (k0 + 16) < Kd;
        if (more) ldAB(k0 + 16);
        mm16(As[buf], Bs[buf], ty8, tx8, acc);
        if (more) { stAB(buf ^ 1); __syncthreads(); buf ^= 1; }
    }

    float4 bs0 = *(const float4*)(bias ? bias + bn + tx8     : nullptr);
    float4 bs1 = *(const float4*)(bias ? bias + bn + tx8 + 4 : nullptr);
    if (!bias) { bs0 = make_float4(0, 0, 0, 0); bs1 = make_float4(0, 0, 0, 0); }

#pragma unroll
    for (int i = 0; i < 8; i++) {
        int r = bm + ty8 + i;
        if (r >= Md) continue;
        float v[8];
#pragma unroll
        for (int j2 = 0; j2 < 4; j2++) unpk(acc[i][j2], v[2 * j2], v[2 * j2 + 1]);
        int c0 = bn + tx8;
        if (MODE == 0) {
            int b = r / N0, ii = r % N0;
            float* dst = g_H + ((long)b * NT + 1 + ii) * EMB + c0;
            *(float4*)dst       = make_float4(v[0] + bs0.x, v[1] + bs0.y, v[2] + bs0.z, v[3] + bs0.w);
            *(float4*)(dst + 4) = make_float4(v[4] + bs1.x, v[5] + bs1.y, v[6] + bs1.z, v[7] + bs1.w);
        } else if (MODE == 1) {
            int b = r / NP, ii = r % NP;
            int part = c0 >> 9;
            int h = (c0 >> 7) & 3;
            int d = c0 & 127;
            float* dst = (part == 0) ? g_Q : (part == 1 ? g_K : g_V);
            float sc = (part == 0) ? QSCALE : 1.f;
            float* o = dst + (((long)b * HEADS + h) * NP + ii) * DH + d;
            *(float4*)o       = make_float4(v[0] * sc, v[1] * sc, v[2] * sc, v[3] * sc);
            *(float4*)(o + 4) = make_float4(v[4] * sc, v[5] * sc, v[6] * sc, v[7] * sc);
        } else {
            int b = r / NT, ii = r % NT;
            float* dst = g_H + ((long)b * NT + ii) * EMB + c0;
            float4 o0 = *(float4*)dst, o1 = *(float4*)(dst + 4);
            o0.x += v[0] + bs0.x; o0.y += v[1] + bs0.y; o0.z += v[2] + bs0.z; o0.w += v[3] + bs0.w;
            o1.x += v[4] + bs1.x; o1.y += v[5] + bs1.y; o1.z += v[6] + bs1.z; o1.w += v[7] + bs1.w;
            *(float4*)dst = o0; *(float4*)(dst + 4) = o1;
        }
    }
}

// ------------------------- host orchestration --------------------------------
static void bgemm(const float* A, const float* Bm, float* C,
                  int M, int N, int K, int lda, int ldb, int ldc,
                  long sA, long sB, long sCb, long sCh,
                  float s, float t, bool transb, bool addt,
                  int split = 1, long sSplit = 0) {
    BG2 p{A, Bm, C, K, lda, ldb, ldc, sA, sB, sCb, sCh, s, t, split, sSplit};
    dim3 g(N / 128, (M + 127) / 128, BATCH * HEADS * split);
    dim3 b(256);
    if (transb)      g128_bat<true,  false><<<g, b>>>(p);
    else if (addt)   g128_bat<false, true ><<<g, b>>>(p);
    else             g128_bat<false, false><<<g, b>>>(p);
}

struct Ptrs {
    float *Q, *K, *V, *QL, *KL, *A1, *A3, *A2, *Za, *Zb, *T1, *T2, *T3, *AV, *AVp, *ZAV, *O;
};

static void run_layer(const Ptrs& P,
                      const float* ln_g, const float* ln_b, const float* qkv_w,
                      const float* out_w, const float* out_b, const float* res_k) {
    ln_pad_kernel<<<BATCH * NP, 256>>>(ln_g, ln_b);
    g128_big<1><<<dim3(3 * EMB / 128, BATCH * NP / 128), 256>>>(nullptr, qkv_w, nullptr);
    landmarks_kernel<<<dim3(LM, BATCH * HEADS), DH>>>();

    // scores + softmax
    bgemm(P.Q,  P.KL, P.A1, NP, LM, DH, DH, DH, LM,
          (long)NP * DH, (long)LM * DH, (long)HEADS * NP * LM, (long)NP * LM, 1.f, 0.f, true, false);
    softmax_rows<1><<<BATCH * HEADS * NP, 256>>>(P.A1, LM, LM);

    bgemm(P.QL, P.KL, P.A2, LM, LM, DH, DH, DH, LM,
          (long)LM * DH, (long)LM * DH, (long)HEADS * LM * LM, (long)LM * LM, 1.f, 0.f, true, false);
    softmax_rows<1><<<BATCH * HEADS * LM, 256>>>(P.A2, LM, LM);

    bgemm(P.QL, P.K,  P.A3, LM, NP, DH, DH, DH, NP,
          (long)LM * DH, (long)NP * DH, (long)HEADS * LM * NP, (long)LM * NP, 1.f, 0.f, true, false);
    softmax_rows<17><<<BATCH * HEADS * LM, 256>>>(P.A3, NP, NP);

    // pinv (Newton-Schulz, 6 iters)
    denom1_kernel<<<BATCH * HEADS, 256>>>();
    denom2_kernel<<<1, 32>>>();
    z0_kernel<<<dim3(LM, BATCH * HEADS), LM>>>(P.Za);
    float* zc = P.Za; float* zn = P.Zb;
    const long S = (long)LM * LM;
    for (int it = 0; it < NITER; it++) {
        bgemm(P.A2, zc,   P.T1, LM, LM, LM, LM, LM, LM, S, S, (long)HEADS * S, S,  1.f,   0.f,  false, false);
        bgemm(P.T1, P.T1, P.T2, LM, LM, LM, LM, LM, LM, S, S, (long)HEADS * S, S, -1.f,   7.f,  false, true);
        bgemm(P.T1, P.T2, P.T3, LM, LM, LM, LM, LM, LM, S, S, (long)HEADS * S, S, -1.f,  15.f,  false, true);
        bgemm(zc,   P.T3, zn,   LM, LM, LM, LM, LM, LM, S, S, (long)HEADS * S, S, -0.25f, 3.25f, false, true);
        float* tmp = zc; zc = zn; zn = tmp;
    }

    // out = a1 @ (z @ (a3 @ v)) ; AV uses split-K=4 into partials
    bgemm(P.A3, P.V,  P.AVp, LM, DH, NP, NP, DH, DH,
          (long)LM * NP, (long)NP * DH, (long)HEADS * LM * DH, (long)LM * DH, 1.f, 0.f, false, false,
          4, (long)BATCH * HEADS * LM * DH);
    av_reduce_kernel<<<(BATCH * HEADS * LM * DH) / 256, 256>>>();

    bgemm(zc,   P.AV, P.ZAV, LM, DH, LM, LM, DH, DH,
          S, (long)LM * DH, (long)HEADS * LM * DH, (long)LM * DH, 1.f, 0.f, false, false);
    bgemm(P.A1, P.ZAV, P.O,  NP, DH, LM, LM, DH, EMB,
          (long)NP * LM, (long)LM * DH, (long)NP * EMB, (long)DH, 1.f, 0.f, false, false);

    resconv_kernel<<<dim3(NP, BATCH * HEADS), DH>>>(res_k);
    g128_big<2><<<dim3(EMB / 128, (BATCH * NT + 127) / 128), 256>>>(nullptr, out_w, out_b);
}

extern "C" void kernel_launch(void* const* d_in, const int* in_sizes, int n_in,
                              void* d_out, int out_size) {
    (void)in_sizes; (void)n_in; (void)out_size;
    const float* X        = (const float*)d_in[0];
    const float* few_w    = (const float*)d_in[1];
    const float* few_b    = (const float*)d_in[2];
    const float* cls_tok  = (const float*)d_in[3];
    const float* l1_ln_g  = (const float*)d_in[4];
    const float* l1_ln_b  = (const float*)d_in[5];
    const float* l1_qkv_w = (const float*)d_in[6];
    const float* l1_out_w = (const float*)d_in[7];
    const float* l1_out_b = (const float*)d_in[8];
    const float* l1_res_k = (const float*)d_in[9];
    const float* l2_ln_g  = (const float*)d_in[10];
    const float* l2_ln_b  = (const float*)d_in[11];
    const float* l2_qkv_w = (const float*)d_in[12];
    const float* l2_out_w = (const float*)d_in[13];
    const float* l2_out_b = (const float*)d_in[14];
    const float* l2_res_k = (const float*)d_in[15];
    const float* k7       = (const float*)d_in[16];
    const float* b7       = (const float*)d_in[17];
    const float* k5       = (const float*)d_in[18];
    const float* b5       = (const float*)d_in[19];
    const float* k3       = (const float*)d_in[20];
    const float* b3       = (const float*)d_in[21];
    const float* norm_g   = (const float*)d_in[22];
    const float* norm_b   = (const float*)d_in[23];
    const float* cls_w    = (const float*)d_in[24];
    const float* cls_b    = (const float*)d_in[25];
    float* out = (float*)d_out;

    Ptrs P;
    cudaGetSymbolAddress((void**)&P.Q,   g_Q);
    cudaGetSymbolAddress((void**)&P.K,   g_K);
    cudaGetSymbolAddress((void**)&P.V,   g_V);
    cudaGetSymbolAddress((void**)&P.QL,  g_QL);
    cudaGetSymbolAddress((void**)&P.KL,  g_KL);
    cudaGetSymbolAddress((void**)&P.A1,  g_A1);
    cudaGetSymbolAddress((void**)&P.A3,  g_A3);
    cudaGetSymbolAddress((void**)&P.A2,  g_A2);
    cudaGetSymbolAddress((void**)&P.Za,  g_Za);
    cudaGetSymbolAddress((void**)&P.Zb,  g_Zb);
    cudaGetSymbolAddress((void**)&P.T1,  g_T1);
    cudaGetSymbolAddress((void**)&P.T2,  g_T2);
    cudaGetSymbolAddress((void**)&P.T3,  g_T3);
    cudaGetSymbolAddress((void**)&P.AV,  g_AV);
    cudaGetSymbolAddress((void**)&P.AVp, g_AVp);
    cudaGetSymbolAddress((void**)&P.ZAV, g_ZAV);
    cudaGetSymbolAddress((void**)&P.O,   g_O);

    // embed + cls token
    set_cls_kernel<<<BATCH, EMB>>>(cls_tok);
    g128_big<0><<<dim3(EMB / 128, BATCH * N0 / 128), 256>>>(X, few_w, few_b);

    // layer 1
    run_layer(P, l1_ln_g, l1_ln_b, l1_qkv_w, l1_out_w, l1_out_b, l1_res_k);

    // PPEG
    ppeg_kernel<<<dim3(N0, BATCH), EMB>>>(k7, b7, k5, b5, k3, b3);
    ppeg_copy_kernel<<<(BATCH * (long)N0 * EMB) / 256, 256>>>();

    // layer 2
    run_layer(P, l2_ln_g, l2_ln_b, l2_qkv_w, l2_out_w, l2_out_b, l2_res_k);

    // final LN + classifier
    final_kernel<<<BATCH, 256>>>(norm_g, norm_b, cls_w, cls_b, out);
}

// round 12
// speedup vs baseline: 1.0011x; 1.0011x over previous
#include <cuda_runtime.h>

#define DF __device__ __forceinline__
typedef unsigned long long ull;

static constexpr int BATCH  = 8;
static constexpr int N0     = 4096;
static constexpr int IN_DIM = 1024;
static constexpr int EMB    = 512;
static constexpr int HEADS  = 4;
static constexpr int DH     = 128;
static constexpr int LM     = 256;    // landmarks
static constexpr int NP     = 4352;   // padded seq
static constexpr int NT     = 4097;   // cls + tokens
static constexpr int PADR   = 255;    // left zero pad
static constexpr int LSEG   = 17;     // NP / LM
static constexpr int NITER  = 6;
static constexpr int RESK   = 33;
static constexpr float QSCALE = 0.08838834764831845f; // 128^-0.5

// ------------------------- scratch (device globals; no allocs) ---------------
__device__ float g_H  [BATCH*NT*EMB];
__device__ float g_LN [BATCH*NP*EMB];
__device__ float g_Q  [BATCH*HEADS*NP*DH];
__device__ float g_K  [BATCH*HEADS*NP*DH];
__device__ float g_V  [BATCH*HEADS*NP*DH];
__device__ float g_QL [BATCH*HEADS*LM*DH];
__device__ float g_KL [BATCH*HEADS*LM*DH];
__device__ float g_A1 [BATCH*HEADS*NP*LM];
__device__ float g_A3 [BATCH*HEADS*LM*NP];
__device__ float g_A2 [BATCH*HEADS*LM*LM];
__device__ float g_Za [BATCH*HEADS*LM*LM];
__device__ float g_Zb [BATCH*HEADS*LM*LM];
__device__ float g_T1 [BATCH*HEADS*LM*LM];
__device__ float g_T2 [BATCH*HEADS*LM*LM];
__device__ float g_T3 [BATCH*HEADS*LM*LM];
__device__ float g_AV [BATCH*HEADS*LM*DH];
__device__ float g_AVp[4*BATCH*HEADS*LM*DH];
__device__ float g_ZAV[BATCH*HEADS*LM*DH];
__device__ float g_O  [BATCH*NP*EMB];
__device__ float g_mr [BATCH*HEADS];
__device__ float g_mc [BATCH*HEADS];
__device__ float g_den[1];

// ------------------------- f32x2 helpers -------------------------------------
DF ull dup2(float x) { ull r; asm("mov.b64 %0, {%1, %1};" : "=l"(r) : "f"(x)); return r; }
DF void ffma2(ull& d, ull a, ull b) {
    asm("fma.rn.f32x2 %0, %1, %2, %0;" : "+l"(d) : "l"(a), "l"(b));
}
DF void unpk(ull v, float& a, float& b) {
    asm("mov.b64 {%0, %1}, %2;" : "=f"(a), "=f"(b) : "l"(v));
}

// ------------------------- block reductions (256 threads) --------------------
DF float blockReduceSum256(float v) {
    __shared__ float sh[256];
    int t = threadIdx.x;
    sh[t] = v; __syncthreads();
#pragma unroll
    for (int s = 128; s > 0; s >>= 1) { if (t < s) sh[t] += sh[t + s]; __syncthreads(); }
    float r = sh[0]; __syncthreads(); return r;
}
DF float blockReduceMax256(float v) {
    __shared__ float sh[256];
    int t = threadIdx.x;
    sh[t] = v; __syncthreads();
#pragma unroll
    for (int s = 128; s > 0; s >>= 1) { if (t < s) sh[t] = fmaxf(sh[t], sh[t + s]); __syncthreads(); }
    float r = sh[0]; __syncthreads(); return r;
}

// ------------------------- misc small kernels --------------------------------
__global__ void set_cls_kernel(const float* __restrict__ cls) {
    g_H[(long)blockIdx.x * NT * EMB + threadIdx.x] = cls[threadIdx.x];
}

__global__ void ln_pad_kernel(const float* __restrict__ g, const float* __restrict__ bt) {
    long row = blockIdx.x;                 // 0 .. BATCH*NP-1
    int b = (int)(row / NP), i = (int)(row % NP);
    float* dst = g_LN + row * EMB;
    int t = threadIdx.x;                   // 256 threads
    if (i < PADR) { dst[t] = 0.f; dst[t + 256] = 0.f; return; }
    const float* src = g_H + ((long)b * NT + (i - PADR)) * EMB;
    float x0 = src[t], x1 = src[t + 256];
    float mu  = blockReduceSum256(x0 + x1) * (1.f / EMB);
    float var = blockReduceSum256(x0 * x0 + x1 * x1) * (1.f / EMB) - mu * mu;
    float rstd = rsqrtf(var + 1e-5f);
    dst[t]       = (x0 - mu) * rstd * g[t]       + bt[t];
    dst[t + 256] = (x1 - mu) * rstd * g[t + 256] + bt[t + 256];
}

__global__ void landmarks_kernel() {
    int z = blockIdx.y, m = blockIdx.x, d = threadIdx.x; // 128 threads
    const float* q = g_Q + ((long)z * NP + m * LSEG) * DH + d;
    const float* k = g_K + ((long)z * NP + m * LSEG) * DH + d;
    float sq = 0.f, sk = 0.f;
#pragma unroll
    for (int j = 0; j < LSEG; j++) { sq += q[(long)j * DH]; sk += k[(long)j * DH]; }
    g_QL[((long)z * LM + m) * DH + d] = sq * (1.f / LSEG);
    g_KL[((long)z * LM + m) * DH + d] = sk * (1.f / LSEG);
}

template <int NIT>
__global__ void softmax_rows(float* __restrict__ base, int cols, int ld) {
    float* p = base + (long)blockIdx.x * ld;
    int t = threadIdx.x;                   // 256 threads
    float v[NIT];
    float mx = -1e30f;
#pragma unroll
    for (int i = 0; i < NIT; i++) {
        int j = i * 256 + t;
        v[i] = (j < cols) ? p[j] : -1e30f;
        mx = fmaxf(mx, v[i]);
    }
    mx = blockReduceMax256(mx);
    float sum = 0.f;
#pragma unroll
    for (int i = 0; i < NIT; i++) {
        int j = i * 256 + t;
        v[i] = (j < cols) ? __expf(v[i] - mx) : 0.f;
        sum += v[i];
    }
    sum = blockReduceSum256(sum);
    float inv = 1.f / sum;
#pragma unroll
    for (int i = 0; i < NIT; i++) {
        int j = i * 256 + t;
        if (j < cols) p[j] = v[i] * inv;
    }
}

__global__ void denom1_kernel() {
    int z = blockIdx.x, t = threadIdx.x;   // 256 threads
    const float* a = g_A2 + (long)z * LM * LM;
    float cs = 0.f, rs = 0.f;
    for (int i = 0; i < LM; i++) cs += fabsf(a[(long)i * LM + t]);
    for (int j = 0; j < LM; j++) rs += fabsf(a[(long)t * LM + j]);
    float mc = blockReduceMax256(cs);
    float mr = blockReduceMax256(rs);
    if (t == 0) { g_mc[z] = mc; g_mr[z] = mr; }
}
__global__ void denom2_kernel() {
    int t = threadIdx.x;                   // 32 threads
    float mc = g_mc[t], mr = g_mr[t];
#pragma unroll
    for (int o = 16; o > 0; o >>= 1) {
        mc = fmaxf(mc, __shfl_down_sync(0xffffffffu, mc, o));
        mr = fmaxf(mr, __shfl_down_sync(0xffffffffu, mr, o));
    }
    if (t == 0) g_den[0] = mc * mr;
}
__global__ void z0_kernel(float* __restrict__ z0) {
    int z = blockIdx.y, m = blockIdx.x, j = threadIdx.x;  // 256 threads
    float inv = 1.f / g_den[0];
    z0[((long)z * LM + m) * LM + j] = g_A2[((long)z * LM + j) * LM + m] * inv;
}

__global__ void resconv_kernel(const float* __restrict__ res_k) {
    int i = blockIdx.x, z = blockIdx.y, d = threadIdx.x;  // 128 threads
    int b = z / HEADS, h = z % HEADS;
    const float* kk = res_k + h * RESK;
    float acc = 0.f;
#pragma unroll
    for (int t = 0; t < RESK; t++) {
        int it = i + t - (RESK / 2);
        if (it >= 0 && it < NP) acc += kk[t] * g_V[((long)z * NP + it) * DH + d];
    }
    g_O[((long)b * NP + i) * EMB + h * DH + d] += acc;
}

__global__ void ppeg_kernel(const float* __restrict__ k7, const float* __restrict__ b7,
                            const float* __restrict__ k5, const float* __restrict__ b5,
                            const float* __restrict__ k3, const float* __restrict__ b3) {
    int pos = blockIdx.x, b = blockIdx.y, c = threadIdx.x; // 512 threads
    int y = pos >> 6, x = pos & 63;
    const float* fb = g_H + ((long)b * NT + 1) * EMB + c;
    float acc = fb[(long)pos * EMB] + b7[c] + b5[c] + b3[c];
    const float* w7 = k7 + c * 49;
#pragma unroll
    for (int ky = 0; ky < 7; ky++) {
        int py = y + ky - 3;
        if ((unsigned)py >= 64u) continue;
#pragma unroll
        for (int kx = 0; kx < 7; kx++) {
            int px = x + kx - 3;
            if ((unsigned)px >= 64u) continue;
            acc += w7[ky * 7 + kx] * fb[(long)(py * 64 + px) * EMB];
        }
    }
    const float* w5 = k5 + c * 25;
#pragma unroll
    for (int ky = 0; ky < 5; ky++) {
        int py = y + ky - 2;
        if ((unsigned)py >= 64u) continue;
#pragma unroll
        for (int kx = 0; kx < 5; kx++) {
            int px = x + kx - 2;
            if ((unsigned)px >= 64u) continue;
            acc += w5[ky * 5 + kx] * fb[(long)(py * 64 + px) * EMB];
        }
    }
    const float* w3 = k3 + c * 9;
#pragma unroll
    for (int ky = 0; ky < 3; ky++) {
        int py = y + ky - 1;
        if ((unsigned)py >= 64u) continue;
#pragma unroll
        for (int kx = 0; kx < 3; kx++) {
            int px = x + kx - 1;
            if ((unsigned)px >= 64u) continue;
            acc += w3[ky * 3 + kx] * fb[(long)(py * 64 + px) * EMB];
        }
    }
    g_LN[((long)b * N0 + pos) * EMB + c] = acc;
}
__global__ void ppeg_copy_kernel() {
    long idx = (long)blockIdx.x * blockDim.x + threadIdx.x;
    long per = (long)N0 * EMB;
    int b = (int)(idx / per); long rem = idx % per;
    g_H[((long)b * NT + 1) * EMB + rem] = g_LN[idx];
}

__global__ void final_kernel(const float* __restrict__ ng, const float* __restrict__ nb,
                             const float* __restrict__ cw, const float* __restrict__ cb,
                             float* __restrict__ out) {
    int b = blockIdx.x, t = threadIdx.x;   // 256 threads
    const float* src = g_H + (long)b * NT * EMB;
    float x0 = src[t], x1 = src[t + 256];
    float mu  = blockReduceSum256(x0 + x1) * (1.f / EMB);
    float var = blockReduceSum256(x0 * x0 + x1 * x1) * (1.f / EMB) - mu * mu;
    float rstd = rsqrtf(var + 1e-5f);
    float v0 = (x0 - mu) * rstd * ng[t]       + nb[t];
    float v1 = (x1 - mu) * rstd * ng[t + 256] + nb[t + 256];
    float dot = blockReduceSum256(v0 * cw[t] + v1 * cw[t + 256]);
    if (t == 0) out[b] = dot + cb[0];
}

__global__ void av_reduce_kernel() {
    long i = (long)blockIdx.x * 256 + threadIdx.x;
    const long T = (long)BATCH * HEADS * LM * DH;
    g_AV[i] = g_AVp[i] + g_AVp[i + T] + g_AVp[i + 2 * T] + g_AVp[i + 3 * T];
}

// ------------------------- 128x128x16 f32x2 inner step -----------------------
DF void mm16(const float (&As)[16][128], const float (&Bs)[16][128],
             int ty8, int tx8, ull (&acc)[8][4]) {
#pragma unroll
    for (int k = 0; k < 16; k++) {
        float4 a0 = *(const float4*)(&As[k][ty8]);
        float4 a1 = *(const float4*)(&As[k][ty8 + 4]);
        ulonglong2 b0 = *(const ulonglong2*)(&Bs[k][tx8]);
        ulonglong2 b1 = *(const ulonglong2*)(&Bs[k][tx8 + 4]);
        ull aD[8];
        aD[0] = dup2(a0.x); aD[1] = dup2(a0.y); aD[2] = dup2(a0.z); aD[3] = dup2(a0.w);
        aD[4] = dup2(a1.x); aD[5] = dup2(a1.y); aD[6] = dup2(a1.z); aD[7] = dup2(a1.w);
        ull bP[4] = {b0.x, b0.y, b1.x, b1.y};
#pragma unroll
        for (int i = 0; i < 8; i++)
#pragma unroll
            for (int j = 0; j < 4; j++) ffma2(acc[i][j], aD[i], bP[j]);
    }
}

// ------------------------- batched GEMM 128x128 ------------------------------
// C = s*(A@B[^T]) + t*A  (batched over z; optional split-K into partial bufs)
struct BG2 {
    const float* A; const float* B; float* C;
    int K, lda, ldb, ldc;
    long sA, sB, sCb, sCh;     // C base = (z/HEADS)*sCb + (z%HEADS)*sCh
    float s, t;
    int split; long sSplit;    // split-K partials
};

template <bool TRANSB, bool ADDT>
__global__ __launch_bounds__(256, 2) void g128_bat(BG2 p) {
    __shared__ float As[2][16][128];
    __shared__ float Bs[2][16][128];

    int zz = blockIdx.z;
    int sp = zz % p.split;
    int z  = zz / p.split;
    const float* Ab = p.A + (long)z * p.sA;
    const float* Bb = p.B + (long)z * p.sB;
    float* Cb = p.C + (long)(z / HEADS) * p.sCb + (long)(z % HEADS) * p.sCh
                    + (long)sp * p.sSplit;
    int kchunk = p.K / p.split;
    int kb = sp * kchunk, ke = kb + kchunk;

    int bm = blockIdx.y * 128, bn = blockIdx.x * 128;
    int tid = threadIdx.x;
    int tx8 = (tid & 15) * 8, ty8 = (tid >> 4) * 8;

    // A loader: m fixed per thread, two k-quads
    int am  = tid & 127;
    int aq0 = (tid >> 7) * 4;             // {0,4}; second load at +8
    const float* Arow = Ab + (long)(bm + am) * p.lda;

    // B loader
    int bkr = 0, bnc = 0, bnr = 0, bq0 = 0;
    const float* Brow = nullptr;
    if (!TRANSB) {
        bkr = tid >> 5;                    // 0..7 (second at +8)
        bnc = (tid & 31) * 4;
    } else {
        bnr = tid & 127;
        bq0 = (tid >> 7) * 4;
        Brow = Bb + (long)(bn + bnr) * p.ldb;
    }

    ull acc[8][4] = {};
    float4 ra0, ra1, rb0, rb1;

    auto ldAB = [&](int k0) {
        ra0 = *(const float4*)(Arow + k0 + aq0);
        ra1 = *(const float4*)(Arow + k0 + aq0 + 8);
        if (!TRANSB) {
            rb0 = *(const float4*)(Bb + (long)(k0 + bkr) * p.ldb + bn + bnc);
            rb1 = *(const float4*)(Bb + (long)(k0 + bkr + 8) * p.ldb + bn + bnc);
        } else {
            rb0 = *(const float4*)(Brow + k0 + bq0);
            rb1 = *(const float4*)(Brow + k0 + bq0 + 8);
        }
    };
    auto stAB = [&](int buf) {
        As[buf][aq0 + 0][am] = ra0.x; As[buf][aq0 + 1][am] = ra0.y;
        As[buf][aq0 + 2][am] = ra0.z; As[buf][aq0 + 3][am] = ra0.w;
        As[buf][aq0 + 8][am] = ra1.x; As[buf][aq0 + 9][am] = ra1.y;
        As[buf][aq0 +10][am] = ra1.z; As[buf][aq0 +11][am] = ra1.w;
        if (!TRANSB) {
            *(float4*)(&Bs[buf][bkr][bnc])     = rb0;
            *(float4*)(&Bs[buf][bkr + 8][bnc]) = rb1;
        } else {
            Bs[buf][bq0 + 0][bnr] = rb0.x; Bs[buf][bq0 + 1][bnr] = rb0.y;
            Bs[buf][bq0 + 2][bnr] = rb0.z; Bs[buf][bq0 + 3][bnr] = rb0.w;
            Bs[buf][bq0 + 8][bnr] = rb1.x; Bs[buf][bq0 + 9][bnr] = rb1.y;
            Bs[buf][bq0 +10][bnr] = rb1.z; Bs[buf][bq0 +11][bnr] = rb1.w;
        }
    };

    ldAB(kb); stAB(0);
    __syncthreads();
    int buf = 0;
    for (int k0 = kb; k0 < ke; k0 += 16) {
        bool more = (k0 + 16) < ke;
        if (more) ldAB(k0 + 16);
        mm16(As[buf], Bs[buf], ty8, tx8, acc);
        if (more) { stAB(buf ^ 1); __syncthreads(); buf ^= 1; }
    }

#pragma unroll
    for (int i = 0; i < 8; i++) {
        long r = bm + ty8 + i;
        float v[8];
#pragma unroll
        for (int j2 = 0; j2 < 4; j2++) unpk(acc[i][j2], v[2 * j2], v[2 * j2 + 1]);
#pragma unroll
        for (int j = 0; j < 8; j++) v[j] *= p.s;
        if (ADDT) {
            float4 t0 = *(const float4*)(Ab + r * p.lda + bn + tx8);
            float4 t1 = *(const float4*)(Ab + r * p.lda + bn + tx8 + 4);
            v[0] += p.t * t0.x; v[1] += p.t * t0.y; v[2] += p.t * t0.z; v[3] += p.t * t0.w;
            v[4] += p.t * t1.x; v[5] += p.t * t1.y; v[6] += p.t * t1.z; v[7] += p.t * t1.w;
        }
        *(float4*)(Cb + r * p.ldc + bn + tx8)     = make_float4(v[0], v[1], v[2], v[3]);
        *(float4*)(Cb + r * p.ldc + bn + tx8 + 4) = make_float4(v[4], v[5], v[6], v[7]);
    }
}

// ------------------------- big weight GEMMs 128x128 --------------------------
// MODE 0: FEW  (X @ few_w + bias) -> g_H rows 1..4096 per batch
// MODE 1: QKV  (g_LN @ qkv_w)     -> scattered to g_Q(*scale)/g_K/g_V
// MODE 2: PROJ (g_O[pad rows] @ out_w + bias) accumulated into g_H
template <int MODE>
__global__ __launch_bounds__(256, 2) void g128_big(const float* __restrict__ Ax,
                                                   const float* __restrict__ W,
                                                   const float* __restrict__ bias) {
    constexpr int Kd = (MODE == 0) ? IN_DIM : EMB;
    constexpr int Nd = (MODE == 1) ? 3 * EMB : EMB;
    constexpr int Md = (MODE == 0) ? BATCH * N0 : (MODE == 1 ? BATCH * NP : BATCH * NT);

    __shared__ float As[2][16][128];
    __shared__ float Bs[2][16][128];

    int bm = blockIdx.y * 128, bn = blockIdx.x * 128;
    int tid = threadIdx.x;
    int tx8 = (tid & 15) * 8, ty8 = (tid >> 4) * 8;

    int am  = tid & 127;
    int aq0 = (tid >> 7) * 4;
    bool avalid = (bm + am) < Md;
    const float* Arow;
    {
        int r = bm + am; if (r >= Md) r = Md - 1;
        if (MODE == 2) {
            int b = r / NT, i = r % NT;
            Arow = g_O + ((long)(b * NP + PADR + i)) * EMB;
        } else if (MODE == 1) {
            Arow = g_LN + (long)r * Kd;
        } else {
            Arow = Ax + (long)r * Kd;
        }
    }
    int bkr = tid >> 5;
    int bnc = (tid & 31) * 4;

    ull acc[8][4] = {};
    float4 ra0, ra1, rb0, rb1;

    auto ldAB = [&](int k0) {
        ra0 = *(const float4*)(Arow + k0 + aq0);
        ra1 = *(const float4*)(Arow + k0 + aq0 + 8);
        if (!avalid) { ra0 = make_float4(0, 0, 0, 0); ra1 = make_float4(0, 0, 0, 0); }
        rb0 = *(const float4*)(W + (long)(k0 + bkr) * Nd + bn + bnc);
        rb1 = *(const float4*)(W + (long)(k0 + bkr + 8) * Nd + bn + bnc);
    };
    auto stAB = [&](int buf) {
        As[buf][aq0 + 0][am] = ra0.x; As[buf][aq0 + 1][am] = ra0.y;
        As[buf][aq0 + 2][am] = ra0.z; As[buf][aq0 + 3][am] = ra0.w;
        As[buf][aq0 + 8][am] = ra1.x; As[buf][aq0 + 9][am] = ra1.y;
        As[buf][aq0 +10][am] = ra1.z; As[buf][aq0 +11][am] = ra1.w;
        *(float4*)(&Bs[buf][bkr][bnc])     = rb0;
        *(float4*)(&Bs[buf][bkr + 8][bnc]) = rb1;
    };

    ldAB(0); stAB(0);
    __syncthreads();
    int buf = 0;
    for (int k0 = 0; k0 < Kd; k0 += 16) {
        bool more = (k0 + 16) < Kd;
        if (more) ldAB(k0 + 16);
        mm16(As[buf], Bs[buf], ty8, tx8, acc);
        if (more) { stAB(buf ^ 1); __syncthreads(); buf ^= 1; }
    }

    float4 bs0 = *(const float4*)(bias ? bias + bn + tx8     : nullptr);
    float4 bs1 = *(const float4*)(bias ? bias + bn + tx8 + 4 : nullptr);
    if (!bias) { bs0 = make_float4(0, 0, 0, 0); bs1 = make_float4(0, 0, 0, 0); }

#pragma unroll
    for (int i = 0; i < 8; i++) {
        int r = bm + ty8 + i;
        if (r >= Md) continue;
        float v[8];
#pragma unroll
        for (int j2 = 0; j2 < 4; j2++) unpk(acc[i][j2], v[2 * j2], v[2 * j2 + 1]);
        int c0 = bn + tx8;
        if (MODE == 0) {
            int b = r / N0, ii = r % N0;
            float* dst = g_H + ((long)b * NT + 1 + ii) * EMB + c0;
            *(float4*)dst       = make_float4(v[0] + bs0.x, v[1] + bs0.y, v[2] + bs0.z, v[3] + bs0.w);
            *(float4*)(dst + 4) = make_float4(v[4] + bs1.x, v[5] + bs1.y, v[6] + bs1.z, v[7] + bs1.w);
        } else if (MODE == 1) {
            int b = r / NP, ii = r % NP;
            int part = c0 >> 9;
            int h = (c0 >> 7) & 3;
            int d = c0 & 127;
            float* dst = (part == 0) ? g_Q : (part == 1 ? g_K : g_V);
            float sc = (part == 0) ? QSCALE : 1.f;
            float* o = dst + (((long)b * HEADS + h) * NP + ii) * DH + d;
            *(float4*)o       = make_float4(v[0] * sc, v[1] * sc, v[2] * sc, v[3] * sc);
            *(float4*)(o + 4) = make_float4(v[4] * sc, v[5] * sc, v[6] * sc, v[7] * sc);
        } else {
            int b = r / NT, ii = r % NT;
            float* dst = g_H + ((long)b * NT + ii) * EMB + c0;
            float4 o0 = *(float4*)dst, o1 = *(float4*)(dst + 4);
            o0.x += v[0] + bs0.x; o0.y += v[1] + bs0.y; o0.z += v[2] + bs0.z; o0.w += v[3] + bs0.w;
            o1.x += v[4] + bs1.x; o1.y += v[5] + bs1.y; o1.z += v[6] + bs1.z; o1.w += v[7] + bs1.w;
            *(float4*)dst = o0; *(float4*)(dst + 4) = o1;
        }
    }
}

// ------------------------- host orchestration --------------------------------
static void bgemm(const float* A, const float* Bm, float* C,
                  int M, int N, int K, int lda, int ldb, int ldc,
                  long sA, long sB, long sCb, long sCh,
                  float s, float t, bool transb, bool addt,
                  int split = 1, long sSplit = 0) {
    BG2 p{A, Bm, C, K, lda, ldb, ldc, sA, sB, sCb, sCh, s, t, split, sSplit};
    dim3 g(N / 128, (M + 127) / 128, BATCH * HEADS * split);
    dim3 b(256);
    if (transb)      g128_bat<true,  false><<<g, b>>>(p);
    else if (addt)   g128_bat<false, true ><<<g, b>>>(p);
    else             g128_bat<false, false><<<g, b>>>(p);
}

struct Ptrs {
    float *Q, *K, *V, *QL, *KL, *A1, *A3, *A2, *Za, *Zb, *T1, *T2, *T3, *AV, *AVp, *ZAV, *O;
};

static void run_layer(const Ptrs& P,
                      const float* ln_g, const float* ln_b, const float* qkv_w,
                      const float* out_w, const float* out_b, const float* res_k) {
    ln_pad_kernel<<<BATCH * NP, 256>>>(ln_g, ln_b);
    g128_big<1><<<dim3(3 * EMB / 128, BATCH * NP / 128), 256>>>(nullptr, qkv_w, nullptr);
    landmarks_kernel<<<dim3(LM, BATCH * HEADS), DH>>>();

    // scores + softmax
    bgemm(P.Q,  P.KL, P.A1, NP, LM, DH, DH, DH, LM,
          (long)NP * DH, (long)LM * DH, (long)HEADS * NP * LM, (long)NP * LM, 1.f, 0.f, true, false);
    softmax_rows<1><<<BATCH * HEADS * NP, 256>>>(P.A1, LM, LM);

    bgemm(P.QL, P.KL, P.A2, LM, LM, DH, DH, DH, LM,
          (long)LM * DH, (long)LM * DH, (long)HEADS * LM * LM, (long)LM * LM, 1.f, 0.f, true, false);
    softmax_rows<1><<<BATCH * HEADS * LM, 256>>>(P.A2, LM, LM);

    bgemm(P.QL, P.K,  P.A3, LM, NP, DH, DH, DH, NP,
          (long)LM * DH, (long)NP * DH, (long)HEADS * LM * NP, (long)LM * NP, 1.f, 0.f, true, false);
    softmax_rows<17><<<BATCH * HEADS * LM, 256>>>(P.A3, NP, NP);

    // pinv (Newton-Schulz, 6 iters)
    denom1_kernel<<<BATCH * HEADS, 256>>>();
    denom2_kernel<<<1, 32>>>();
    z0_kernel<<<dim3(LM, BATCH * HEADS), LM>>>(P.Za);
    float* zc = P.Za; float* zn = P.Zb;
    const long S = (long)LM * LM;
    for (int it = 0; it < NITER; it++) {
        bgemm(P.A2, zc,   P.T1, LM, LM, LM, LM, LM, LM, S, S, (long)HEADS * S, S,  1.f,   0.f,  false, false);
        bgemm(P.T1, P.T1, P.T2, LM, LM, LM, LM, LM, LM, S, S, (long)HEADS * S, S, -1.f,   7.f,  false, true);
        bgemm(P.T1, P.T2, P.T3, LM, LM, LM, LM, LM, LM, S, S, (long)HEADS * S, S, -1.f,  15.f,  false, true);
        bgemm(zc,   P.T3, zn,   LM, LM, LM, LM, LM, LM, S, S, (long)HEADS * S, S, -0.25f, 3.25f, false, true);
        float* tmp = zc; zc = zn; zn = tmp;
    }

    // out = a1 @ (z @ (a3 @ v)) ; AV uses split-K=4 into partials
    bgemm(P.A3, P.V,  P.AVp, LM, DH, NP, NP, DH, DH,
          (long)LM * NP, (long)NP * DH, (long)HEADS * LM * DH, (long)LM * DH, 1.f, 0.f, false, false,
          4, (long)BATCH * HEADS * LM * DH);
    av_reduce_kernel<<<(BATCH * HEADS * LM * DH) / 256, 256>>>();

    bgemm(zc,   P.AV, P.ZAV, LM, DH, LM, LM, DH, DH,
          S, (long)LM * DH, (long)HEADS * LM * DH, (long)LM * DH, 1.f, 0.f, false, false);
    bgemm(P.A1, P.ZAV, P.O,  NP, DH, LM, LM, DH, EMB,
          (long)NP * LM, (long)LM * DH, (long)NP * EMB, (long)DH, 1.f, 0.f, false, false);

    resconv_kernel<<<dim3(NP, BATCH * HEADS), DH>>>(res_k);
    g128_big<2><<<dim3(EMB / 128, (BATCH * NT + 127) / 128), 256>>>(nullptr, out_w, out_b);
}

extern "C" void kernel_launch(void* const* d_in, const int* in_sizes, int n_in,
                              void* d_out, int out_size) {
    (void)in_sizes; (void)n_in; (void)out_size;
    const float* X        = (const float*)d_in[0];
    const float* few_w    = (const float*)d_in[1];
    const float* few_b    = (const float*)d_in[2];
    const float* cls_tok  = (const float*)d_in[3];
    const float* l1_ln_g  = (const float*)d_in[4];
    const float* l1_ln_b  = (const float*)d_in[5];
    const float* l1_qkv_w = (const float*)d_in[6];
    const float* l1_out_w = (const float*)d_in[7];
    const float* l1_out_b = (const float*)d_in[8];
    const float* l1_res_k = (const float*)d_in[9];
    const float* l2_ln_g  = (const float*)d_in[10];
    const float* l2_ln_b  = (const float*)d_in[11];
    const float* l2_qkv_w = (const float*)d_in[12];
    const float* l2_out_w = (const float*)d_in[13];
    const float* l2_out_b = (const float*)d_in[14];
    const float* l2_res_k = (const float*)d_in[15];
    const float* k7       = (const float*)d_in[16];
    const float* b7       = (const float*)d_in[17];
    const float* k5       = (const float*)d_in[18];
    const float* b5       = (const float*)d_in[19];
    const float* k3       = (const float*)d_in[20];
    const float* b3       = (const float*)d_in[21];
    const float* norm_g   = (const float*)d_in[22];
    const float* norm_b   = (const float*)d_in[23];
    const float* cls_w    = (const float*)d_in[24];
    const float* cls_b    = (const float*)d_in[25];
    float* out = (float*)d_out;

    Ptrs P;
    cudaGetSymbolAddress((void**)&P.Q,   g_Q);
    cudaGetSymbolAddress((void**)&P.K,   g_K);
    cudaGetSymbolAddress((void**)&P.V,   g_V);
    cudaGetSymbolAddress((void**)&P.QL,  g_QL);
    cudaGetSymbolAddress((void**)&P.KL,  g_KL);
    cudaGetSymbolAddress((void**)&P.A1,  g_A1);
    cudaGetSymbolAddress((void**)&P.A3,  g_A3);
    cudaGetSymbolAddress((void**)&P.A2,  g_A2);
    cudaGetSymbolAddress((void**)&P.Za,  g_Za);
    cudaGetSymbolAddress((void**)&P.Zb,  g_Zb);
    cudaGetSymbolAddress((void**)&P.T1,  g_T1);
    cudaGetSymbolAddress((void**)&P.T2,  g_T2);
    cudaGetSymbolAddress((void**)&P.T3,  g_T3);
    cudaGetSymbolAddress((void**)&P.AV,  g_AV);
    cudaGetSymbolAddress((void**)&P.AVp, g_AVp);
    cudaGetSymbolAddress((void**)&P.ZAV, g_ZAV);
    cudaGetSymbolAddress((void**)&P.O,   g_O);

    // embed + cls token
    set_cls_kernel<<<BATCH, EMB>>>(cls_tok);
    g128_big<0><<<dim3(EMB / 128, BATCH * N0 / 128), 256>>>(X, few_w, few_b);

    // layer 1
    run_layer(P, l1_ln_g, l1_ln_b, l1_qkv_w, l1_out_w, l1_out_b, l1_res_k);

    // PPEG
    ppeg_kernel<<<dim3(N0, BATCH), EMB>>>(k7, b7, k5, b5, k3, b3);
    ppeg_copy_kernel<<<(BATCH * (long)N0 * EMB) / 256, 256>>>();

    // layer 2
    run_layer(P, l2_ln_g, l2_ln_b, l2_qkv_w, l2_out_w, l2_out_b, l2_res_k);

    // final LN + classifier
    final_kernel<<<BATCH, 256>>>(norm_g, norm_b, cls_w, cls_b, out);
}

// round 13
// speedup vs baseline: 1.0020x; 1.0009x over previous
#include <cuda_runtime.h>

#define DF __device__ __forceinline__
typedef unsigned long long ull;

static constexpr int BATCH  = 8;
static constexpr int N0     = 4096;
static constexpr int IN_DIM = 1024;
static constexpr int EMB    = 512;
static constexpr int HEADS  = 4;
static constexpr int DH     = 128;
static constexpr int LM     = 256;    // landmarks
static constexpr int NP     = 4352;   // padded seq
static constexpr int NT     = 4097;   // cls + tokens
static constexpr int PADR   = 255;    // left zero pad
static constexpr int LSEG   = 17;     // NP / LM
static constexpr int NITER  = 6;
static constexpr int RESK   = 33;
static constexpr float QSCALE = 0.08838834764831845f; // 128^-0.5

// ------------------------- scratch (device globals; no allocs) ---------------
__device__ float g_H  [BATCH*NT*EMB];
__device__ float g_LN [BATCH*NP*EMB];
__device__ float g_Q  [BATCH*HEADS*NP*DH];
__device__ float g_K  [BATCH*HEADS*NP*DH];
__device__ float g_V  [BATCH*HEADS*NP*DH];
__device__ float g_QL [BATCH*HEADS*LM*DH];
__device__ float g_KL [BATCH*HEADS*LM*DH];
__device__ float g_A1 [BATCH*HEADS*NP*LM];
__device__ float g_A3 [BATCH*HEADS*LM*NP];
__device__ float g_A2 [BATCH*HEADS*LM*LM];
__device__ float g_Za [BATCH*HEADS*LM*LM];
__device__ float g_Zb [BATCH*HEADS*LM*LM];
__device__ float g_T1 [BATCH*HEADS*LM*LM];
__device__ float g_T2 [BATCH*HEADS*LM*LM];
__device__ float g_T3 [BATCH*HEADS*LM*LM];
__device__ float g_AV [BATCH*HEADS*LM*DH];
__device__ float g_AVp[4*BATCH*HEADS*LM*DH];
__device__ float g_ZAV[BATCH*HEADS*LM*DH];
__device__ float g_O  [BATCH*NP*EMB];
__device__ float g_mr [BATCH*HEADS];
__device__ float g_mc [BATCH*HEADS];
__device__ float g_den[1];

// ------------------------- f32x2 helpers -------------------------------------
DF ull dup2(float x) { ull r; asm("mov.b64 %0, {%1, %1};" : "=l"(r) : "f"(x)); return r; }
DF void ffma2(ull& d, ull a, ull b) {
    asm("fma.rn.f32x2 %0, %1, %2, %0;" : "+l"(d) : "l"(a), "l"(b));
}
DF void unpk(ull v, float& a, float& b) {
    asm("mov.b64 {%0, %1}, %2;" : "=f"(a), "=f"(b) : "l"(v));
}

// ------------------------- block reductions (256 threads) --------------------
DF float blockReduceSum256(float v) {
    __shared__ float sh[256];
    int t = threadIdx.x;
    sh[t] = v; __syncthreads();
#pragma unroll
    for (int s = 128; s > 0; s >>= 1) { if (t < s) sh[t] += sh[t + s]; __syncthreads(); }
    float r = sh[0]; __syncthreads(); return r;
}
DF float blockReduceMax256(float v) {
    __shared__ float sh[256];
    int t = threadIdx.x;
    sh[t] = v; __syncthreads();
#pragma unroll
    for (int s = 128; s > 0; s >>= 1) { if (t < s) sh[t] = fmaxf(sh[t], sh[t + s]); __syncthreads(); }
    float r = sh[0]; __syncthreads(); return r;
}

// ------------------------- misc small kernels --------------------------------
__global__ void set_cls_kernel(const float* __restrict__ cls) {
    g_H[(long)blockIdx.x * NT * EMB + threadIdx.x] = cls[threadIdx.x];
}

__global__ void ln_pad_kernel(const float* __restrict__ g, const float* __restrict__ bt) {
    long row = blockIdx.x;                 // 0 .. BATCH*NP-1
    int b = (int)(row / NP), i = (int)(row % NP);
    float* dst = g_LN + row * EMB;
    int t = threadIdx.x;                   // 256 threads
    if (i < PADR) { dst[t] = 0.f; dst[t + 256] = 0.f; return; }
    const float* src = g_H + ((long)b * NT + (i - PADR)) * EMB;
    float x0 = src[t], x1 = src[t + 256];
    float mu  = blockReduceSum256(x0 + x1) * (1.f / EMB);
    float var = blockReduceSum256(x0 * x0 + x1 * x1) * (1.f / EMB) - mu * mu;
    float rstd = rsqrtf(var + 1e-5f);
    dst[t]       = (x0 - mu) * rstd * g[t]       + bt[t];
    dst[t + 256] = (x1 - mu) * rstd * g[t + 256] + bt[t + 256];
}

__global__ void landmarks_kernel() {
    int z = blockIdx.y, m = blockIdx.x, d = threadIdx.x; // 128 threads
    const float* q = g_Q + ((long)z * NP + m * LSEG) * DH + d;
    const float* k = g_K + ((long)z * NP + m * LSEG) * DH + d;
    float sq = 0.f, sk = 0.f;
#pragma unroll
    for (int j = 0; j < LSEG; j++) { sq += q[(long)j * DH]; sk += k[(long)j * DH]; }
    g_QL[((long)z * LM + m) * DH + d] = sq * (1.f / LSEG);
    g_KL[((long)z * LM + m) * DH + d] = sk * (1.f / LSEG);
}

template <int NIT>
__global__ void softmax_rows(float* __restrict__ base, int cols, int ld) {
    float* p = base + (long)blockIdx.x * ld;
    int t = threadIdx.x;                   // 256 threads
    float v[NIT];
    float mx = -1e30f;
#pragma unroll
    for (int i = 0; i < NIT; i++) {
        int j = i * 256 + t;
        v[i] = (j < cols) ? p[j] : -1e30f;
        mx = fmaxf(mx, v[i]);
    }
    mx = blockReduceMax256(mx);
    float sum = 0.f;
#pragma unroll
    for (int i = 0; i < NIT; i++) {
        int j = i * 256 + t;
        v[i] = (j < cols) ? __expf(v[i] - mx) : 0.f;
        sum += v[i];
    }
    sum = blockReduceSum256(sum);
    float inv = 1.f / sum;
#pragma unroll
    for (int i = 0; i < NIT; i++) {
        int j = i * 256 + t;
        if (j < cols) p[j] = v[i] * inv;
    }
}

__global__ void denom1_kernel() {
    int z = blockIdx.x, t = threadIdx.x;   // 256 threads
    const float* a = g_A2 + (long)z * LM * LM;
    float cs = 0.f, rs = 0.f;
    for (int i = 0; i < LM; i++) cs += fabsf(a[(long)i * LM + t]);
    for (int j = 0; j < LM; j++) rs += fabsf(a[(long)t * LM + j]);
    float mc = blockReduceMax256(cs);
    float mr = blockReduceMax256(rs);
    if (t == 0) { g_mc[z] = mc; g_mr[z] = mr; }
}
__global__ void denom2_kernel() {
    int t = threadIdx.x;                   // 32 threads
    float mc = g_mc[t], mr = g_mr[t];
#pragma unroll
    for (int o = 16; o > 0; o >>= 1) {
        mc = fmaxf(mc, __shfl_down_sync(0xffffffffu, mc, o));
        mr = fmaxf(mr, __shfl_down_sync(0xffffffffu, mr, o));
    }
    if (t == 0) g_den[0] = mc * mr;
}
__global__ void z0_kernel(float* __restrict__ z0) {
    int z = blockIdx.y, m = blockIdx.x, j = threadIdx.x;  // 256 threads
    float inv = 1.f / g_den[0];
    z0[((long)z * LM + m) * LM + j] = g_A2[((long)z * LM + j) * LM + m] * inv;
}

__global__ void resconv_kernel(const float* __restrict__ res_k) {
    int i = blockIdx.x, z = blockIdx.y, d = threadIdx.x;  // 128 threads
    int b = z / HEADS, h = z % HEADS;
    const float* kk = res_k + h * RESK;
    float acc = 0.f;
#pragma unroll
    for (int t = 0; t < RESK; t++) {
        int it = i + t - (RESK / 2);
        if (it >= 0 && it < NP) acc += kk[t] * g_V[((long)z * NP + it) * DH + d];
    }
    g_O[((long)b * NP + i) * EMB + h * DH + d] += acc;
}

__global__ void ppeg_kernel(const float* __restrict__ k7, const float* __restrict__ b7,
                            const float* __restrict__ k5, const float* __restrict__ b5,
                            const float* __restrict__ k3, const float* __restrict__ b3) {
    int pos = blockIdx.x, b = blockIdx.y, c = threadIdx.x; // 512 threads
    int y = pos >> 6, x = pos & 63;
    const float* fb = g_H + ((long)b * NT + 1) * EMB + c;
    float acc = fb[(long)pos * EMB] + b7[c] + b5[c] + b3[c];
    const float* w7 = k7 + c * 49;
#pragma unroll
    for (int ky = 0; ky < 7; ky++) {
        int py = y + ky - 3;
        if ((unsigned)py >= 64u) continue;
#pragma unroll
        for (int kx = 0; kx < 7; kx++) {
            int px = x + kx - 3;
            if ((unsigned)px >= 64u) continue;
            acc += w7[ky * 7 + kx] * fb[(long)(py * 64 + px) * EMB];
        }
    }
    const float* w5 = k5 + c * 25;
#pragma unroll
    for (int ky = 0; ky < 5; ky++) {
        int py = y + ky - 2;
        if ((unsigned)py >= 64u) continue;
#pragma unroll
        for (int kx = 0; kx < 5; kx++) {
            int px = x + kx - 2;
            if ((unsigned)px >= 64u) continue;
            acc += w5[ky * 5 + kx] * fb[(long)(py * 64 + px) * EMB];
        }
    }
    const float* w3 = k3 + c * 9;
#pragma unroll
    for (int ky = 0; ky < 3; ky++) {
        int py = y + ky - 1;
        if ((unsigned)py >= 64u) continue;
#pragma unroll
        for (int kx = 0; kx < 3; kx++) {
            int px = x + kx - 1;
            if ((unsigned)px >= 64u) continue;
            acc += w3[ky * 3 + kx] * fb[(long)(py * 64 + px) * EMB];
        }
    }
    g_LN[((long)b * N0 + pos) * EMB + c] = acc;
}
__global__ void ppeg_copy_kernel() {
    long idx = (long)blockIdx.x * blockDim.x + threadIdx.x;
    long per = (long)N0 * EMB;
    int b = (int)(idx / per); long rem = idx % per;
    g_H[((long)b * NT + 1) * EMB + rem] = g_LN[idx];
}

__global__ void final_kernel(const float* __restrict__ ng, const float* __restrict__ nb,
                             const float* __restrict__ cw, const float* __restrict__ cb,
                             float* __restrict__ out) {
    int b = blockIdx.x, t = threadIdx.x;   // 256 threads
    const float* src = g_H + (long)b * NT * EMB;
    float x0 = src[t], x1 = src[t + 256];
    float mu  = blockReduceSum256(x0 + x1) * (1.f / EMB);
    float var = blockReduceSum256(x0 * x0 + x1 * x1) * (1.f / EMB) - mu * mu;
    float rstd = rsqrtf(var + 1e-5f);
    float v0 = (x0 - mu) * rstd * ng[t]       + nb[t];
    float v1 = (x1 - mu) * rstd * ng[t + 256] + nb[t + 256];
    float dot = blockReduceSum256(v0 * cw[t] + v1 * cw[t + 256]);
    if (t == 0) out[b] = dot + cb[0];
}

__global__ void av_reduce_kernel() {
    long i = (long)blockIdx.x * 256 + threadIdx.x;
    const long T = (long)BATCH * HEADS * LM * DH;
    g_AV[i] = g_AVp[i] + g_AVp[i + T] + g_AVp[i + 2 * T] + g_AVp[i + 3 * T];
}

// ------------------------- 128x128x16 f32x2 inner step -----------------------
DF void mm16(const float (&As)[16][128], const float (&Bs)[16][128],
             int ty8, int tx8, ull (&acc)[8][4]) {
#pragma unroll
    for (int k = 0; k < 16; k++) {
        float4 a0 = *(const float4*)(&As[k][ty8]);
        float4 a1 = *(const float4*)(&As[k][ty8 + 4]);
        ulonglong2 b0 = *(const ulonglong2*)(&Bs[k][tx8]);
        ulonglong2 b1 = *(const ulonglong2*)(&Bs[k][tx8 + 4]);
        ull aD[8];
        aD[0] = dup2(a0.x); aD[1] = dup2(a0.y); aD[2] = dup2(a0.z); aD[3] = dup2(a0.w);
        aD[4] = dup2(a1.x); aD[5] = dup2(a1.y); aD[6] = dup2(a1.z); aD[7] = dup2(a1.w);
        ull bP[4] = {b0.x, b0.y, b1.x, b1.y};
#pragma unroll
        for (int i = 0; i < 8; i++)
#pragma unroll
            for (int j = 0; j < 4; j++) ffma2(acc[i][j], aD[i], bP[j]);
    }
}

// ------------------------- batched GEMM 128x128 ------------------------------
// C = s*(A@B[^T]) + t*A  (batched over z; optional split-K into partial bufs)
struct BG2 {
    const float* A; const float* B; float* C;
    int K, lda, ldb, ldc;
    long sA, sB, sCb, sCh;     // C base = (z/HEADS)*sCb + (z%HEADS)*sCh
    float s, t;
    int split; long sSplit;    // split-K partials
};

template <bool TRANSB, bool ADDT>
__global__ __launch_bounds__(256, 2) void g128_bat(BG2 p) {
    __shared__ float As[2][16][128];
    __shared__ float Bs[2][16][128];

    int zz = blockIdx.z;
    int sp = zz % p.split;
    int z  = zz / p.split;
    const float* Ab = p.A + (long)z * p.sA;
    const float* Bb = p.B + (long)z * p.sB;
    float* Cb = p.C + (long)(z / HEADS) * p.sCb + (long)(z % HEADS) * p.sCh
                    + (long)sp * p.sSplit;
    int kchunk = p.K / p.split;
    int kb = sp * kchunk, ke = kb + kchunk;

    int bm = blockIdx.y * 128, bn = blockIdx.x * 128;
    int tid = threadIdx.x;
    int tx8 = (tid & 15) * 8, ty8 = (tid >> 4) * 8;

    // A loader: m fixed per thread, two k-quads
    int am  = tid & 127;
    int aq0 = (tid >> 7) * 4;             // {0,4}; second load at +8
    const float* Arow = Ab + (long)(bm + am) * p.lda;

    // B loader
    int bkr = 0, bnc = 0, bnr = 0, bq0 = 0;
    const float* Brow = nullptr;
    if (!TRANSB) {
        bkr = tid >> 5;                    // 0..7 (second at +8)
        bnc = (tid & 31) * 4;
    } else {
        bnr = tid & 127;
        bq0 = (tid >> 7) * 4;
        Brow = Bb + (long)(bn + bnr) * p.ldb;
    }

    ull acc[8][4] = {};
    float4 ra0, ra1, rb0, rb1;

    auto ldAB = [&](int k0) {
        ra0 = *(const float4*)(Arow + k0 + aq0);
        ra1 = *(const float4*)(Arow + k0 + aq0 + 8);
        if (!TRANSB) {
            rb0 = *(const float4*)(Bb + (long)(k0 + bkr) * p.ldb + bn + bnc);
            rb1 = *(const float4*)(Bb + (long)(k0 + bkr + 8) * p.ldb + bn + bnc);
        } else {
            rb0 = *(const float4*)(Brow + k0 + bq0);
            rb1 = *(const float4*)(Brow + k0 + bq0 + 8);
        }
    };
    auto stAB = [&](int buf) {
        As[buf][aq0 + 0][am] = ra0.x; As[buf][aq0 + 1][am] = ra0.y;
        As[buf][aq0 + 2][am] = ra0.z; As[buf][aq0 + 3][am] = ra0.w;
        As[buf][aq0 + 8][am] = ra1.x; As[buf][aq0 + 9][am] = ra1.y;
        As[buf][aq0 +10][am] = ra1.z; As[buf][aq0 +11][am] = ra1.w;
        if (!TRANSB) {
            *(float4*)(&Bs[buf][bkr][bnc])     = rb0;
            *(float4*)(&Bs[buf][bkr + 8][bnc]) = rb1;
        } else {
            Bs[buf][bq0 + 0][bnr] = rb0.x; Bs[buf][bq0 + 1][bnr] = rb0.y;
            Bs[buf][bq0 + 2][bnr] = rb0.z; Bs[buf][bq0 + 3][bnr] = rb0.w;
            Bs[buf][bq0 + 8][bnr] = rb1.x; Bs[buf][bq0 + 9][bnr] = rb1.y;
            Bs[buf][bq0 +10][bnr] = rb1.z; Bs[buf][bq0 +11][bnr] = rb1.w;
        }
    };

    ldAB(kb); stAB(0);
    __syncthreads();
    int buf = 0;
    for (int k0 = kb; k0 < ke; k0 += 16) {
        bool more = (k0 + 16) < ke;
        if (more) ldAB(k0 + 16);
        mm16(As[buf], Bs[buf], ty8, tx8, acc);
        if (more) { stAB(buf ^ 1); __syncthreads(); buf ^= 1; }
    }

#pragma unroll
    for (int i = 0; i < 8; i++) {
        long r = bm + ty8 + i;
        float v[8];
#pragma unroll
        for (int j2 = 0; j2 < 4; j2++) unpk(acc[i][j2], v[2 * j2], v[2 * j2 + 1]);
#pragma unroll
        for (int j = 0; j < 8; j++) v[j] *= p.s;
        if (ADDT) {
            float4 t0 = *(const float4*)(Ab + r * p.lda + bn + tx8);
            float4 t1 = *(const float4*)(Ab + r * p.lda + bn + tx8 + 4);
            v[0] += p.t * t0.x; v[1] += p.t * t0.y; v[2] += p.t * t0.z; v[3] += p.t * t0.w;
            v[4] += p.t * t1.x; v[5] += p.t * t1.y; v[6] += p.t * t1.z; v[7] += p.t * t1.w;
        }
        *(float4*)(Cb + r * p.ldc + bn + tx8)     = make_float4(v[0], v[1], v[2], v[3]);
        *(float4*)(Cb + r * p.ldc + bn + tx8 + 4) = make_float4(v[4], v[5], v[6], v[7]);
    }
}

// ------------------------- big weight GEMMs 128x128 --------------------------
// MODE 0: FEW  (X @ few_w + bias) -> g_H rows 1..4096 per batch
// MODE 1: QKV  (g_LN @ qkv_w)     -> scattered to g_Q(*scale)/g_K/g_V
// MODE 2: PROJ (g_O[pad rows] @ out_w + bias) accumulated into g_H
template <int MODE>
__global__ __launch_bounds__(256, 2) void g128_big(const float* __restrict__ Ax,
                                                   const float* __restrict__ W,
                                                   const float* __restrict__ bias) {
    constexpr int Kd = (MODE == 0) ? IN_DIM : EMB;
    constexpr int Nd = (MODE == 1) ? 3 * EMB : EMB;
    constexpr int Md = (MODE == 0) ? BATCH * N0 : (MODE == 1 ? BATCH * NP : BATCH * NT);

    __shared__ float As[2][16][128];
    __shared__ float Bs[2][16][128];

    int bm = blockIdx.y * 128, bn = blockIdx.x * 128;
    int tid = threadIdx.x;
    int tx8 = (tid & 15) * 8, ty8 = (tid >> 4) * 8;

    int am  = tid & 127;
    int aq0 = (tid >> 7) * 4;
    bool avalid = (bm + am) < Md;
    const float* Arow;
    {
        int r = bm + am; if (r >= Md) r = Md - 1;
        if (MODE == 2) {
            int b = r / NT, i = r % NT;
            Arow = g_O + ((long)(b * NP + PADR + i)) * EMB;
        } else if (MODE == 1) {
            Arow = g_LN + (long)r * Kd;
        } else {
            Arow = Ax + (long)r * Kd;
        }
    }
    int bkr = tid >> 5;
    int bnc = (tid & 31) * 4;

    ull acc[8][4] = {};
    float4 ra0, ra1, rb0, rb1;

    auto ldAB = [&](int k0) {
        ra0 = *(const float4*)(Arow + k0 + aq0);
        ra1 = *(const float4*)(Arow + k0 + aq0 + 8);
        if (!avalid) { ra0 = make_float4(0, 0, 0, 0); ra1 = make_float4(0, 0, 0, 0); }
        rb0 = *(const float4*)(W + (long)(k0 + bkr) * Nd + bn + bnc);
        rb1 = *(const float4*)(W + (long)(k0 + bkr + 8) * Nd + bn + bnc);
    };
    auto stAB = [&](int buf) {
        As[buf][aq0 + 0][am] = ra0.x; As[buf][aq0 + 1][am] = ra0.y;
        As[buf][aq0 + 2][am] = ra0.z; As[buf][aq0 + 3][am] = ra0.w;
        As[buf][aq0 + 8][am] = ra1.x; As[buf][aq0 + 9][am] = ra1.y;
        As[buf][aq0 +10][am] = ra1.z; As[buf][aq0 +11][am] = ra1.w;
        *(float4*)(&Bs[buf][bkr][bnc])     = rb0;
        *(float4*)(&Bs[buf][bkr + 8][bnc]) = rb1;
    };

    ldAB(0); stAB(0);
    __syncthreads();
    int buf = 0;
    for (int k0 = 0; k0 < Kd; k0 += 16) {
        bool more = (k0 + 16) < Kd;
        if (more) ldAB(k0 + 16);
        mm16(As[buf], Bs[buf], ty8, tx8, acc);
        if (more) { stAB(buf ^ 1); __syncthreads(); buf ^= 1; }
    }

    float4 bs0 = *(const float4*)(bias ? bias + bn + tx8     : nullptr);
    float4 bs1 = *(const float4*)(bias ? bias + bn + tx8 + 4 : nullptr);
    if (!bias) { bs0 = make_float4(0, 0, 0, 0); bs1 = make_float4(0, 0, 0, 0); }

#pragma unroll
    for (int i = 0; i < 8; i++) {
        int r = bm + ty8 + i;
        if (r >= Md) continue;
        float v[8];
#pragma unroll
        for (int j2 = 0; j2 < 4; j2++) unpk(acc[i][j2], v[2 * j2], v[2 * j2 + 1]);
        int c0 = bn + tx8;
        if (MODE == 0) {
            int b = r / N0, ii = r % N0;
            float* dst = g_H + ((long)b * NT + 1 + ii) * EMB + c0;
            *(float4*)dst       = make_float4(v[0] + bs0.x, v[1] + bs0.y, v[2] + bs0.z, v[3] + bs0.w);
            *(float4*)(dst + 4) = make_float4(v[4] + bs1.x, v[5] + bs1.y, v[6] + bs1.z, v[7] + bs1.w);
        } else if (MODE == 1) {
            int b = r / NP, ii = r % NP;
            int part = c0 >> 9;
            int h = (c0 >> 7) & 3;
            int d = c0 & 127;
            float* dst = (part == 0) ? g_Q : (part == 1 ? g_K : g_V);
            float sc = (part == 0) ? QSCALE : 1.f;
            float* o = dst + (((long)b * HEADS + h) * NP + ii) * DH + d;
            *(float4*)o       = make_float4(v[0] * sc, v[1] * sc, v[2] * sc, v[3] * sc);
            *(float4*)(o + 4) = make_float4(v[4] * sc, v[5] * sc, v[6] * sc, v[7] * sc);
        } else {
            int b = r / NT, ii = r % NT;
            float* dst = g_H + ((long)b * NT + ii) * EMB + c0;
            float4 o0 = *(float4*)dst, o1 = *(float4*)(dst + 4);
            o0.x += v[0] + bs0.x; o0.y += v[1] + bs0.y; o0.z += v[2] + bs0.z; o0.w += v[3] + bs0.w;
            o1.x += v[4] + bs1.x; o1.y += v[5] + bs1.y; o1.z += v[6] + bs1.z; o1.w += v[7] + bs1.w;
            *(float4*)dst = o0; *(float4*)(dst + 4) = o1;
        }
    }
}

// ------------------------- host orchestration --------------------------------
static void bgemm(const float* A, const float* Bm, float* C,
                  int M, int N, int K, int lda, int ldb, int ldc,
                  long sA, long sB, long sCb, long sCh,
                  float s, float t, bool transb, bool addt,
                  int split = 1, long sSplit = 0) {
    BG2 p{A, Bm, C, K, lda, ldb, ldc, sA, sB, sCb, sCh, s, t, split, sSplit};
    dim3 g(N / 128, (M + 127) / 128, BATCH * HEADS * split);
    dim3 b(256);
    if (transb)      g128_bat<true,  false><<<g, b>>>(p);
    else if (addt)   g128_bat<false, true ><<<g, b>>>(p);
    else             g128_bat<false, false><<<g, b>>>(p);
}

struct Ptrs {
    float *Q, *K, *V, *QL, *KL, *A1, *A3, *A2, *Za, *Zb, *T1, *T2, *T3, *AV, *AVp, *ZAV, *O;
};

static void run_layer(const Ptrs& P,
                      const float* ln_g, const float* ln_b, const float* qkv_w,
                      const float* out_w, const float* out_b, const float* res_k) {
    ln_pad_kernel<<<BATCH * NP, 256>>>(ln_g, ln_b);
    g128_big<1><<<dim3(3 * EMB / 128, BATCH * NP / 128), 256>>>(nullptr, qkv_w, nullptr);
    landmarks_kernel<<<dim3(LM, BATCH * HEADS), DH>>>();

    // scores + softmax
    bgemm(P.Q,  P.KL, P.A1, NP, LM, DH, DH, DH, LM,
          (long)NP * DH, (long)LM * DH, (long)HEADS * NP * LM, (long)NP * LM, 1.f, 0.f, true, false);
    softmax_rows<1><<<BATCH * HEADS * NP, 256>>>(P.A1, LM, LM);

    bgemm(P.QL, P.KL, P.A2, LM, LM, DH, DH, DH, LM,
          (long)LM * DH, (long)LM * DH, (long)HEADS * LM * LM, (long)LM * LM, 1.f, 0.f, true, false);
    softmax_rows<1><<<BATCH * HEADS * LM, 256>>>(P.A2, LM, LM);

    bgemm(P.QL, P.K,  P.A3, LM, NP, DH, DH, DH, NP,
          (long)LM * DH, (long)NP * DH, (long)HEADS * LM * NP, (long)LM * NP, 1.f, 0.f, true, false);
    softmax_rows<17><<<BATCH * HEADS * LM, 256>>>(P.A3, NP, NP);

    // pinv (Newton-Schulz, 6 iters)
    denom1_kernel<<<BATCH * HEADS, 256>>>();
    denom2_kernel<<<1, 32>>>();
    z0_kernel<<<dim3(LM, BATCH * HEADS), LM>>>(P.Za);
    float* zc = P.Za; float* zn = P.Zb;
    const long S = (long)LM * LM;
    for (int it = 0; it < NITER; it++) {
        bgemm(P.A2, zc,   P.T1, LM, LM, LM, LM, LM, LM, S, S, (long)HEADS * S, S,  1.f,   0.f,  false, false);
        bgemm(P.T1, P.T1, P.T2, LM, LM, LM, LM, LM, LM, S, S, (long)HEADS * S, S, -1.f,   7.f,  false, true);
        bgemm(P.T1, P.T2, P.T3, LM, LM, LM, LM, LM, LM, S, S, (long)HEADS * S, S, -1.f,  15.f,  false, true);
        bgemm(zc,   P.T3, zn,   LM, LM, LM, LM, LM, LM, S, S, (long)HEADS * S, S, -0.25f, 3.25f, false, true);
        float* tmp = zc; zc = zn; zn = tmp;
    }

    // out = a1 @ (z @ (a3 @ v)) ; AV uses split-K=4 into partials
    bgemm(P.A3, P.V,  P.AVp, LM, DH, NP, NP, DH, DH,
          (long)LM * NP, (long)NP * DH, (long)HEADS * LM * DH, (long)LM * DH, 1.f, 0.f, false, false,
          4, (long)BATCH * HEADS * LM * DH);
    av_reduce_kernel<<<(BATCH * HEADS * LM * DH) / 256, 256>>>();

    bgemm(zc,   P.AV, P.ZAV, LM, DH, LM, LM, DH, DH,
          S, (long)LM * DH, (long)HEADS * LM * DH, (long)LM * DH, 1.f, 0.f, false, false);
    bgemm(P.A1, P.ZAV, P.O,  NP, DH, LM, LM, DH, EMB,
          (long)NP * LM, (long)LM * DH, (long)NP * EMB, (long)DH, 1.f, 0.f, false, false);

    resconv_kernel<<<dim3(NP, BATCH * HEADS), DH>>>(res_k);
    g128_big<2><<<dim3(EMB / 128, (BATCH * NT + 127) / 128), 256>>>(nullptr, out_w, out_b);
}

extern "C" void kernel_launch(void* const* d_in, const int* in_sizes, int n_in,
                              void* d_out, int out_size) {
    (void)in_sizes; (void)n_in; (void)out_size;
    const float* X        = (const float*)d_in[0];
    const float* few_w    = (const float*)d_in[1];
    const float* few_b    = (const float*)d_in[2];
    const float* cls_tok  = (const float*)d_in[3];
    const float* l1_ln_g  = (const float*)d_in[4];
    const float* l1_ln_b  = (const float*)d_in[5];
    const float* l1_qkv_w = (const float*)d_in[6];
    const float* l1_out_w = (const float*)d_in[7];
    const float* l1_out_b = (const float*)d_in[8];
    const float* l1_res_k = (const float*)d_in[9];
    const float* l2_ln_g  = (const float*)d_in[10];
    const float* l2_ln_b  = (const float*)d_in[11];
    const float* l2_qkv_w = (const float*)d_in[12];
    const float* l2_out_w = (const float*)d_in[13];
    const float* l2_out_b = (const float*)d_in[14];
    const float* l2_res_k = (const float*)d_in[15];
    const float* k7       = (const float*)d_in[16];
    const float* b7       = (const float*)d_in[17];
    const float* k5       = (const float*)d_in[18];
    const float* b5       = (const float*)d_in[19];
    const float* k3       = (const float*)d_in[20];
    const float* b3       = (const float*)d_in[21];
    const float* norm_g   = (const float*)d_in[22];
    const float* norm_b   = (const float*)d_in[23];
    const float* cls_w    = (const float*)d_in[24];
    const float* cls_b    = (const float*)d_in[25];
    float* out = (float*)d_out;

    Ptrs P;
    cudaGetSymbolAddress((void**)&P.Q,   g_Q);
    cudaGetSymbolAddress((void**)&P.K,   g_K);
    cudaGetSymbolAddress((void**)&P.V,   g_V);
    cudaGetSymbolAddress((void**)&P.QL,  g_QL);
    cudaGetSymbolAddress((void**)&P.KL,  g_KL);
    cudaGetSymbolAddress((void**)&P.A1,  g_A1);
    cudaGetSymbolAddress((void**)&P.A3,  g_A3);
    cudaGetSymbolAddress((void**)&P.A2,  g_A2);
    cudaGetSymbolAddress((void**)&P.Za,  g_Za);
    cudaGetSymbolAddress((void**)&P.Zb,  g_Zb);
    cudaGetSymbolAddress((void**)&P.T1,  g_T1);
    cudaGetSymbolAddress((void**)&P.T2,  g_T2);
    cudaGetSymbolAddress((void**)&P.T3,  g_T3);
    cudaGetSymbolAddress((void**)&P.AV,  g_AV);
    cudaGetSymbolAddress((void**)&P.AVp, g_AVp);
    cudaGetSymbolAddress((void**)&P.ZAV, g_ZAV);
    cudaGetSymbolAddress((void**)&P.O,   g_O);

    // embed + cls token
    set_cls_kernel<<<BATCH, EMB>>>(cls_tok);
    g128_big<0><<<dim3(EMB / 128, BATCH * N0 / 128), 256>>>(X, few_w, few_b);

    // layer 1
    run_layer(P, l1_ln_g, l1_ln_b, l1_qkv_w, l1_out_w, l1_out_b, l1_res_k);

    // PPEG
    ppeg_kernel<<<dim3(N0, BATCH), EMB>>>(k7, b7, k5, b5, k3, b3);
    ppeg_copy_kernel<<<(BATCH * (long)N0 * EMB) / 256, 256>>>();

    // layer 2
    run_layer(P, l2_ln_g, l2_ln_b, l2_qkv_w, l2_out_w, l2_out_b, l2_res_k);

    // final LN + classifier
    final_kernel<<<BATCH, 256>>>(norm_g, norm_b, cls_w, cls_b, out);
}